// round 16
// baseline (speedup 1.0000x reference)
#include <cuda_runtime.h>
#include <cuda_fp16.h>
#include <cstdint>

#define BB 2
#define SS 2048
#define HH 1024
#define NH 16
#define HD 64
#define ZT (BB * NH)
#define EROWS 4096   // 4095 used + 1 zero pad row

// fp16 operands
__device__ __half g_qh[ZT * SS * HD], g_kh[ZT * SS * HD], g_vh[ZT * SS * HD];
__device__ __half g_eh[EROWS * HD];
// fp16 copies of GEMM inputs
__device__ __half g_h16[BB * SS * HH];          // hidden  [4096][1024]
__device__ __half g_w16[HH * 3 * HH];           // qkv_w   [1024][3072]
// per-row softmax stats: (max, 1/sum)
__device__ float2 g_rowstat[ZT * SS];

#define SW128(o) ((o) ^ (((o) >> 3) & 0x70))

__device__ __forceinline__ uint32_t smem_u32(const void* p) {
    uint32_t a;
    asm("{ .reg .u64 t; cvta.to.shared.u64 t, %1; cvt.u32.u64 %0, t; }"
        : "=r"(a) : "l"(p));
    return a;
}
__device__ __forceinline__ void ldsm4(uint32_t r[4], uint32_t addr) {
    asm volatile("ldmatrix.sync.aligned.m8n8.x4.shared.b16 {%0,%1,%2,%3}, [%4];"
        : "=r"(r[0]), "=r"(r[1]), "=r"(r[2]), "=r"(r[3]) : "r"(addr));
}
__device__ __forceinline__ void ldsm4t(uint32_t r[4], uint32_t addr) {
    asm volatile("ldmatrix.sync.aligned.m8n8.x4.trans.shared.b16 {%0,%1,%2,%3}, [%4];"
        : "=r"(r[0]), "=r"(r[1]), "=r"(r[2]), "=r"(r[3]) : "r"(addr));
}
__device__ __forceinline__ void mma_f16(float c[4], const uint32_t a[4],
                                        const uint32_t b[2]) {
    asm volatile(
        "mma.sync.aligned.m16n8k16.row.col.f32.f16.f16.f32 "
        "{%0,%1,%2,%3}, {%4,%5,%6,%7}, {%8,%9}, {%0,%1,%2,%3};"
        : "+f"(c[0]), "+f"(c[1]), "+f"(c[2]), "+f"(c[3])
        : "r"(a[0]), "r"(a[1]), "r"(a[2]), "r"(a[3]), "r"(b[0]), "r"(b[1]));
}
__device__ __forceinline__ void cp16(uint32_t smem_addr, const void* gptr) {
    asm volatile("cp.async.cg.shared.global [%0], [%1], 16;"
                 :: "r"(smem_addr), "l"(gptr));
}

// ---------------------------------------------------------------------------
// Convert kernels: fp32 -> fp16
// ---------------------------------------------------------------------------
__global__ __launch_bounds__(256) void conv_h_kernel(const float* __restrict__ src)
{
    int i = blockIdx.x * 256 + threadIdx.x;
    float4 v = ((const float4*)src)[i];
    ((__half2*)g_h16)[2 * i] = __floats2half2_rn(v.x, v.y);
    ((__half2*)g_h16)[2 * i + 1] = __floats2half2_rn(v.z, v.w);
}
__global__ __launch_bounds__(256) void conv_w_kernel(const float* __restrict__ src)
{
    int i = blockIdx.x * 256 + threadIdx.x;
    float4 v = ((const float4*)src)[i];
    ((__half2*)g_w16)[2 * i] = __floats2half2_rn(v.x, v.y);
    ((__half2*)g_w16)[2 * i + 1] = __floats2half2_rn(v.z, v.w);
}

// ---------------------------------------------------------------------------
// Kernel 1: QKV projection on HMMA (unchanged from R8, verified 79us).
// ---------------------------------------------------------------------------
#define QKO_A 0
#define QKO_W 32768
#define QK_SMEM 65536

__global__ __launch_bounds__(256, 2) void qkv_mma_kernel(
    const float* __restrict__ bias)
{
    extern __shared__ char smem[];
    const uint32_t sb = smem_u32(smem);
    const int tid = threadIdx.x, wid = tid >> 5, lane = tid & 31;
    const int bx = blockIdx.x, by = blockIdx.y;
    const int m0 = (wid >> 1) * 32;
    const int wx = wid & 1;

    auto fill = [&](int s, int kt) {
        const uint32_t stgA = sb + QKO_A + s * 16384;
        const uint32_t stgW = sb + QKO_W + s * 16384;
#pragma unroll
        for (int j = 0; j < 4; j++) {
            int idx = tid + 256 * j;
            int row = idx >> 3, c = idx & 7;
            cp16(stgA + SW128((uint32_t)(row * 128 + c * 16)),
                 g_h16 + (size_t)(by * 128 + row) * HH + kt * 64 + c * 8);
        }
#pragma unroll
        for (int j = 0; j < 4; j++) {
            int idx = tid + 256 * j;
            int row = idx >> 4, c = idx & 15;
            cp16(stgW + (c >> 3) * 8192 + SW128((uint32_t)(row * 128 + (c & 7) * 16)),
                 g_w16 + (size_t)(kt * 64 + row) * 3072 + bx * 128 + c * 8);
        }
        asm volatile("cp.async.commit_group;" ::: "memory");
    };

    float acc[2][8][4];
#pragma unroll
    for (int i = 0; i < 2; i++)
#pragma unroll
        for (int j = 0; j < 8; j++)
#pragma unroll
            for (int c = 0; c < 4; c++) acc[i][j][c] = 0.f;

    const int aRow = lane & 15;
    const int aBx = (lane >> 4) * 16;

    fill(0, 0);
    fill(1, 1);

    for (int kt = 0; kt < 16; kt++) {
        if (kt < 15) asm volatile("cp.async.wait_group 1;" ::: "memory");
        else         asm volatile("cp.async.wait_group 0;" ::: "memory");
        __syncthreads();

        const uint32_t stgA = sb + QKO_A + (kt & 1) * 16384;
        const uint32_t wsub = sb + QKO_W + (kt & 1) * 16384 + wx * 8192;
#pragma unroll
        for (int ks = 0; ks < 4; ks++) {
            uint32_t Af[2][4], Bf[4][4];
#pragma unroll
            for (int mf = 0; mf < 2; mf++)
                ldsm4(Af[mf], stgA +
                      SW128((uint32_t)((m0 + mf * 16 + aRow) * 128 + ks * 32 + aBx)));
#pragma unroll
            for (int nt = 0; nt < 4; nt++)
                ldsm4t(Bf[nt], wsub +
                       SW128((uint32_t)((ks * 16 + aRow) * 128 + nt * 32 + aBx)));
#pragma unroll
            for (int mf = 0; mf < 2; mf++)
#pragma unroll
                for (int nf = 0; nf < 8; nf++)
                    mma_f16(acc[mf][nf], Af[mf], &Bf[nf >> 1][(nf & 1) * 2]);
        }
        __syncthreads();
        if (kt + 2 < 16) fill(kt & 1, kt + 2);
    }

    const int r = lane >> 2, c2 = 2 * (lane & 3);
#pragma unroll
    for (int nf = 0; nf < 8; nf++) {
        int n = bx * 128 + wx * 64 + nf * 8 + c2;
        float b0 = bias[n], b1 = bias[n + 1];
        int which = n >> 10;
        int h = (n & 1023) >> 6;
        int d = n & 63;
        __half* dst = (which == 0) ? g_qh : (which == 1) ? g_kh : g_vh;
#pragma unroll
        for (int mf = 0; mf < 2; mf++) {
            int m = by * 128 + m0 + mf * 16 + r;
            int b = m >> 11, s = m & 2047;
            size_t off = ((size_t)(b * NH + h) * SS + s) * HD + d;
            *(__half2*)(dst + off) =
                __floats2half2_rn(acc[mf][nf][0] + b0, acc[mf][nf][1] + b1);
            *(__half2*)(dst + off + (size_t)8 * HD) =
                __floats2half2_rn(acc[mf][nf][2] + b0, acc[mf][nf][3] + b1);
        }
    }
}

// ---------------------------------------------------------------------------
// Kernel 1b: dist_emb -> fp16 (row 4095 zero-padded)
// ---------------------------------------------------------------------------
__global__ __launch_bounds__(256) void split_e_kernel(const float* __restrict__ dist_emb)
{
    int i = blockIdx.x * 256 + threadIdx.x;
    if (i >= EROWS * HD) return;
    float e = (i < 4095 * HD) ? dist_emb[i] : 0.f;
    g_eh[i] = __float2half_rn(e);
}

// ---------------------------------------------------------------------------
// Kernel 2: persistent score kernel, 32-l-row tiles, 384 thr, 2 CTAs/SM.
// (unchanged from R12/R13, verified)  Writes RAW scores + g_rowstat.
// ---------------------------------------------------------------------------
#define SCQ 0
#define SCK 4096
#define SCE 20480
#define SCS 45056
#define SCQE 53760
#define SCKE 60416
#define SCMASK 73728
#define SC_SMEM 81920

__global__ __launch_bounds__(384, 2) void score_mma_kernel(
    const float* __restrict__ mask, float* __restrict__ probs)
{
    extern __shared__ char smem[];
    const uint32_t sb = smem_u32(smem);
    const int tid = threadIdx.x, wid = tid >> 5, lane = tid & 31;
    const int l0 = blockIdx.x * 32;
    const int z = blockIdx.y;

    for (int i = tid; i < 512; i += 384)
        ((float4*)(smem + SCMASK))[i] =
            ((const float4*)(mask + (size_t)(z / NH) * SS))[i];
    if (tid < 256) {
        int row = tid >> 3, c = tid & 7;
        uint32_t so = SW128((uint32_t)(row * 128 + c * 16));
        *(uint4*)(smem + SCQ + so) =
            *(const uint4*)(g_qh + ((size_t)z * SS + l0 + row) * HD + c * 8);
    }

    auto fill = [&](int s, int rt) {
        const uint32_t kbuf = sb + SCK + s * 8192;
        const uint32_t ebuf = sb + SCE + s * 12288;
        const int base2 = l0 - rt * 64 + 1984;
        for (int i = tid; i < 1280; i += 384) {
            if (i < 512) {
                int row = i >> 3, c = i & 7;
                cp16(kbuf + SW128((uint32_t)(row * 128 + c * 16)),
                     g_kh + ((size_t)z * SS + rt * 64 + row) * HD + c * 8);
            } else {
                int j = i - 512;
                int row = j >> 3, c = j & 7;
                cp16(ebuf + SW128((uint32_t)(row * 128 + c * 16)),
                     g_eh + (size_t)(base2 + row) * HD + c * 8);
            }
        }
        asm volatile("cp.async.commit_group;" ::: "memory");
    };

    fill(0, 0);
    fill(1, 1);

    const bool mma_act = (wid < 11);
    const bool aIsQ = (wid < 5);
    const int m0 = aIsQ ? 0 : ((wid - 5) & 1) * 32;
    const bool bIsK = (wid < 2);
    const int bn0 = (wid < 2) ? wid * 32
                  : (wid < 5) ? (wid - 2) * 32
                  : ((wid - 5) >> 1) * 32;

    const int aRow = lane & 15;
    const int aBx = (lane >> 4) * 16;
    const int bRow = (lane & 7) + (lane >> 4) * 8;
    const int bBx = ((lane >> 3) & 1) * 16;

    float om = -1e30f, os = 0.f;

    for (int r0 = 0; r0 < 32; r0++) {
        if (r0 < 31) asm volatile("cp.async.wait_group 1;" ::: "memory");
        else         asm volatile("cp.async.wait_group 0;" ::: "memory");
        __syncthreads();

        const int cur = r0 & 1;
        const uint32_t kbuf = sb + SCK + cur * 8192;
        const uint32_t ebuf = sb + SCE + cur * 12288;

        if (mma_act) {
            const uint32_t aBase = aIsQ ? (sb + SCQ) : kbuf;
            const uint32_t bBase = bIsK ? kbuf : ebuf;

            float acc[2][4][4];
#pragma unroll
            for (int i = 0; i < 2; i++)
#pragma unroll
                for (int j = 0; j < 4; j++)
#pragma unroll
                    for (int c = 0; c < 4; c++) acc[i][j][c] = 0.f;

#pragma unroll
            for (int ks = 0; ks < 4; ks++) {
                const int kb = ks * 32;
                uint32_t Af[2][4], Bf[2][4];
#pragma unroll
                for (int mf = 0; mf < 2; mf++)
                    ldsm4(Af[mf], aBase +
                          SW128((uint32_t)((m0 + mf * 16 + aRow) * 128 + kb + aBx)));
#pragma unroll
                for (int nt = 0; nt < 2; nt++)
                    ldsm4(Bf[nt], bBase +
                          SW128((uint32_t)((bn0 + nt * 16 + bRow) * 128 + kb + bBx)));
#pragma unroll
                for (int mf = 0; mf < 2; mf++)
#pragma unroll
                    for (int nf = 0; nf < 4; nf++)
                        mma_f16(acc[mf][nf], Af[mf], &Bf[nf >> 1][(nf & 1) * 2]);
            }

            const int r = lane >> 2, c2 = 2 * (lane & 3);
            if (bIsK) {
                float* sp = (float*)(smem + SCS);
#pragma unroll
                for (int mf = 0; mf < 2; mf++) {
                    int u = mf * 16 + r;
#pragma unroll
                    for (int nf = 0; nf < 4; nf++) {
                        int cc = bn0 + nf * 8 + c2;
                        *(float2*)&sp[u * 68 + cc] =
                            make_float2(acc[mf][nf][0], acc[mf][nf][1]);
                        *(float2*)&sp[(u + 8) * 68 + cc] =
                            make_float2(acc[mf][nf][2], acc[mf][nf][3]);
                    }
                }
            } else if (aIsQ) {
                __half* sp = (__half*)(smem + SCQE);
#pragma unroll
                for (int mf = 0; mf < 2; mf++) {
                    int u = mf * 16 + r;
#pragma unroll
                    for (int nf = 0; nf < 4; nf++) {
                        int cc = bn0 + nf * 8 + c2;
                        *(__half2*)&sp[u * 104 + cc] =
                            __floats2half2_rn(acc[mf][nf][0], acc[mf][nf][1]);
                        *(__half2*)&sp[(u + 8) * 104 + cc] =
                            __floats2half2_rn(acc[mf][nf][2], acc[mf][nf][3]);
                    }
                }
            } else {
                __half* sp = (__half*)(smem + SCKE);
#pragma unroll
                for (int mf = 0; mf < 2; mf++) {
                    int v = m0 + mf * 16 + r;
#pragma unroll
                    for (int nf = 0; nf < 4; nf++) {
                        int cc = bn0 + nf * 8 + c2;
                        *(__half2*)&sp[v * 104 + cc] =
                            __floats2half2_rn(acc[mf][nf][0], acc[mf][nf][1]);
                        *(__half2*)&sp[(v + 8) * 104 + cc] =
                            __floats2half2_rn(acc[mf][nf][2], acc[mf][nf][3]);
                    }
                }
            }
        }
        __syncthreads();

        if (r0 + 2 < 32) fill(cur, r0 + 2);

        if (tid < 256) {
            const float* Ss  = (const float*)(smem + SCS);
            const __half* QEs = (const __half*)(smem + SCQE);
            const __half* KEs = (const __half*)(smem + SCKE);
            const float* msk = (const float*)(smem + SCMASK);
            const int u = tid >> 3;
            const int v0 = (tid & 7) * 8;
            float* orow = probs + ((size_t)z * SS + l0 + u) * SS + r0 * 64;

            float4 o[2];
#pragma unroll
            for (int g = 0; g < 2; g++) {
                float* po = (float*)&o[g];
#pragma unroll
                for (int c = 0; c < 4; c++) {
                    int v = v0 + g * 4 + c;
                    int j = u - v + 63;
                    po[c] = 0.125f * Ss[u * 68 + v]
                          + __half2float(QEs[u * 104 + j])
                          + __half2float(KEs[v * 104 + j])
                          + msk[r0 * 64 + v];
                }
            }
            float tm = fmaxf(fmaxf(fmaxf(o[0].x, o[0].y), fmaxf(o[0].z, o[0].w)),
                             fmaxf(fmaxf(o[1].x, o[1].y), fmaxf(o[1].z, o[1].w)));
            float mn = fmaxf(om, tm);
            float add = __expf(o[0].x - mn) + __expf(o[0].y - mn)
                      + __expf(o[0].z - mn) + __expf(o[0].w - mn)
                      + __expf(o[1].x - mn) + __expf(o[1].y - mn)
                      + __expf(o[1].z - mn) + __expf(o[1].w - mn);
            os = os * __expf(om - mn) + add;
            om = mn;

            *(float4*)(orow + v0) = o[0];
            *(float4*)(orow + v0 + 4) = o[1];
        }
    }

    if (tid < 256) {
#pragma unroll
        for (int d = 4; d > 0; d >>= 1) {
            float m2 = __shfl_xor_sync(0xFFFFFFFF, om, d);
            float s2 = __shfl_xor_sync(0xFFFFFFFF, os, d);
            float mn = fmaxf(om, m2);
            os = os * __expf(om - mn) + s2 * __expf(m2 - mn);
            om = mn;
        }
        if ((tid & 7) == 0)
            g_rowstat[(size_t)z * SS + l0 + (tid >> 3)] = make_float2(om, 1.f / os);
    }
}

// ---------------------------------------------------------------------------
// Kernel 3: FUSED normalize + PV, v2 (all phase inputs cp.async-staged).
// Block (z, 128 l-rows), 32 chunks of 64 r-cols.
// Smem: PRAW 2x34816 | P16 16384 | V 3x8192 | stats 1024 = 111616 -> 2 CTA/SM.
// ---------------------------------------------------------------------------
#define PF_PRAW 0
#define PF_P16 69632
#define PF_V 86016
#define PF_STAT 110592
#define PF_SMEM 111616

__global__ __launch_bounds__(256) void pv_fused_kernel(
    float* __restrict__ probs, float* __restrict__ ctx)
{
    extern __shared__ char smem[];
    const uint32_t sb = smem_u32(smem);
    const int tid = threadIdx.x, wid = tid >> 5, lane = tid & 31;
    const int z = blockIdx.y;
    const int l0 = blockIdx.x * 128;
    const int m0 = (wid >> 1) * 32, d0 = (wid & 1) * 32;

    const size_t pbase = ((size_t)z * SS + l0) * SS;
    const size_t vbase = (size_t)z * SS * HD;
    float2* stats = (float2*)(smem + PF_STAT);

    if (tid < 128)
        stats[tid] = g_rowstat[(size_t)z * SS + l0 + tid];

    auto fill = [&](int c, int ps, int vs) {
        const uint32_t praw = sb + PF_PRAW + ps * 34816;
#pragma unroll
        for (int j = 0; j < 8; j++) {
            int idx = tid + 256 * j;
            int row = idx >> 4, c4 = idx & 15;
            cp16(praw + (uint32_t)(row * 272 + c4 * 16),
                 probs + pbase + (size_t)row * SS + c * 64 + c4 * 4);
        }
        const uint32_t vstg = sb + PF_V + vs * 8192;
#pragma unroll
        for (int j = 0; j < 2; j++) {
            int idx = tid + 256 * j;
            int row = idx >> 3, cc = idx & 7;
            cp16(vstg + SW128((uint32_t)(row * 128 + cc * 16)),
                 g_vh + vbase + (size_t)(c * 64 + row) * HD + cc * 8);
        }
        asm volatile("cp.async.commit_group;" ::: "memory");
    };

    float acc[2][4][4];
#pragma unroll
    for (int i = 0; i < 2; i++)
#pragma unroll
        for (int j = 0; j < 4; j++)
#pragma unroll
            for (int c = 0; c < 4; c++) acc[i][j][c] = 0.f;

    const int aRow = lane & 15;
    const int aBx = (lane >> 4) * 16;

    fill(0, 0, 0);
    fill(1, 1, 1);

    for (int it = 0; it < 32; it++) {
        if (it < 31) asm volatile("cp.async.wait_group 1;" ::: "memory");
        else         asm volatile("cp.async.wait_group 0;" ::: "memory");
        __syncthreads();            // A: chunk it staged; MMA(it-1) done

        // convert from SMEM: exp*inv -> global fp32 (final) + fp16 P16
        {
            const char* praw = smem + PF_PRAW + (it & 1) * 34816;
            float* pout = probs + pbase + it * 64;
#pragma unroll
            for (int j = 0; j < 8; j++) {
                int idx = tid + 256 * j;
                int row = idx >> 4, c4 = idx & 15;
                float2 st = stats[row];
                float4 x = *(const float4*)(praw + row * 272 + c4 * 16);
                x.x = __expf(x.x - st.x) * st.y;
                x.y = __expf(x.y - st.x) * st.y;
                x.z = __expf(x.z - st.x) * st.y;
                x.w = __expf(x.w - st.x) * st.y;
                *(float4*)(pout + (size_t)row * SS + c4 * 4) = x;
                __half2 h0 = __floats2half2_rn(x.x, x.y);
                __half2 h1 = __floats2half2_rn(x.z, x.w);
                *(uint2*)(smem + PF_P16 +
                          SW128((uint32_t)(row * 128 + c4 * 8))) =
                    make_uint2(*(uint32_t*)&h0, *(uint32_t*)&h1);
            }
        }
        __syncthreads();            // B: P16 ready; PRAW[it&1] consumed

        if (it + 2 < 32) fill(it + 2, it & 1, (it + 2) % 3);

        // MMA: P16 (k=64) x V stage it%3  (verified R12 structure)
        const uint32_t vsub = sb + PF_V + (it % 3) * 8192;
#pragma unroll
        for (int ks = 0; ks < 4; ks++) {
            const int kb = ks * 32;
            uint32_t Af[2][4], Bf[2][4];
#pragma unroll
            for (int mf = 0; mf < 2; mf++)
                ldsm4(Af[mf], sb + PF_P16 +
                      SW128((uint32_t)((m0 + mf * 16 + aRow) * 128 + kb + aBx)));
#pragma unroll
            for (int nt = 0; nt < 2; nt++)
                ldsm4t(Bf[nt], vsub +
                       SW128((uint32_t)((ks * 16 + aRow) * 128 + (d0 + nt * 16) * 2 + aBx)));
#pragma unroll
            for (int mf = 0; mf < 2; mf++)
#pragma unroll
                for (int nf = 0; nf < 4; nf++)
                    mma_f16(acc[mf][nf], Af[mf], &Bf[nf >> 1][(nf & 1) * 2]);
        }
    }

    const int b = z / NH, h = z % NH;
    const int r = lane >> 2, c2 = 2 * (lane & 3);
#pragma unroll
    for (int mf = 0; mf < 2; mf++) {
        int l = l0 + m0 + mf * 16 + r;
#pragma unroll
        for (int nf = 0; nf < 4; nf++) {
            int d = d0 + nf * 8 + c2;
            float* o = ctx + ((size_t)b * SS + l) * HH + h * HD + d;
            *(float2*)o = make_float2(acc[mf][nf][0], acc[mf][nf][1]);
            *(float2*)(o + (size_t)8 * HH) = make_float2(acc[mf][nf][2], acc[mf][nf][3]);
        }
    }
}

// ---------------------------------------------------------------------------
extern "C" void kernel_launch(void* const* d_in, const int* in_sizes, int n_in,
                              void* d_out, int out_size)
{
    const float* hidden   = (const float*)d_in[0];
    const float* mask     = (const float*)d_in[1];
    const float* qkv_w    = (const float*)d_in[2];
    const float* qkv_b    = (const float*)d_in[3];
    const float* dist_emb = (const float*)d_in[4];

    float* out = (float*)d_out;
    float* ctx = out;
    float* probs = out + (size_t)BB * SS * HH;

    // 1) fp16 conversions of GEMM inputs + E table
    conv_h_kernel<<<BB * SS * HH / 1024, 256>>>(hidden);
    conv_w_kernel<<<HH * 3 * HH / 1024, 256>>>(qkv_w);
    split_e_kernel<<<(EROWS * HD + 255) / 256, 256>>>(dist_emb);

    // 2) QKV projection on HMMA -> g_qh/g_kh/g_vh
    cudaFuncSetAttribute(qkv_mma_kernel,
                         cudaFuncAttributeMaxDynamicSharedMemorySize, QK_SMEM);
    qkv_mma_kernel<<<dim3(3072 / 128, 4096 / 128), 256, QK_SMEM>>>(qkv_b);

    // 3) persistent warp-MMA scores -> RAW probs + g_rowstat
    cudaFuncSetAttribute(score_mma_kernel,
                         cudaFuncAttributeMaxDynamicSharedMemorySize, SC_SMEM);
    score_mma_kernel<<<dim3(SS / 32, ZT), 384, SC_SMEM>>>(mask, probs);

    // 4) fused normalize + PV (cp.async-staged): probs normalized in place,
    //    ctx = P @ V
    cudaFuncSetAttribute(pv_fused_kernel,
                         cudaFuncAttributeMaxDynamicSharedMemorySize, PF_SMEM);
    pv_fused_kernel<<<dim3(SS / 128, ZT), 256, PF_SMEM>>>(probs, ctx);
}

// round 17
// speedup vs baseline: 1.3572x; 1.3572x over previous
#include <cuda_runtime.h>
#include <cuda_fp16.h>
#include <cstdint>

#define BB 2
#define SS 2048
#define HH 1024
#define NH 16
#define HD 64
#define ZT (BB * NH)
#define EROWS 4096   // 4095 used + 1 zero pad row

// fp16 operands
__device__ __half g_qh[ZT * SS * HD], g_kh[ZT * SS * HD], g_vh[ZT * SS * HD];
__device__ __half g_eh[EROWS * HD];
__device__ __half g_ph[(size_t)ZT * SS * SS];   // fp16 probs (normalize -> pv)
// fp16 copies of GEMM inputs
__device__ __half g_h16[BB * SS * HH];          // hidden  [4096][1024]
__device__ __half g_w16[HH * 3 * HH];           // qkv_w   [1024][3072]
// per-row softmax stats: (max, 1/sum)
__device__ float2 g_rowstat[ZT * SS];

#define SW128(o) ((o) ^ (((o) >> 3) & 0x70))

__device__ __forceinline__ uint32_t smem_u32(const void* p) {
    uint32_t a;
    asm("{ .reg .u64 t; cvta.to.shared.u64 t, %1; cvt.u32.u64 %0, t; }"
        : "=r"(a) : "l"(p));
    return a;
}
__device__ __forceinline__ void ldsm4(uint32_t r[4], uint32_t addr) {
    asm volatile("ldmatrix.sync.aligned.m8n8.x4.shared.b16 {%0,%1,%2,%3}, [%4];"
        : "=r"(r[0]), "=r"(r[1]), "=r"(r[2]), "=r"(r[3]) : "r"(addr));
}
__device__ __forceinline__ void ldsm4t(uint32_t r[4], uint32_t addr) {
    asm volatile("ldmatrix.sync.aligned.m8n8.x4.trans.shared.b16 {%0,%1,%2,%3}, [%4];"
        : "=r"(r[0]), "=r"(r[1]), "=r"(r[2]), "=r"(r[3]) : "r"(addr));
}
__device__ __forceinline__ void mma_f16(float c[4], const uint32_t a[4],
                                        const uint32_t b[2]) {
    asm volatile(
        "mma.sync.aligned.m16n8k16.row.col.f32.f16.f16.f32 "
        "{%0,%1,%2,%3}, {%4,%5,%6,%7}, {%8,%9}, {%0,%1,%2,%3};"
        : "+f"(c[0]), "+f"(c[1]), "+f"(c[2]), "+f"(c[3])
        : "r"(a[0]), "r"(a[1]), "r"(a[2]), "r"(a[3]), "r"(b[0]), "r"(b[1]));
}
__device__ __forceinline__ void cp16(uint32_t smem_addr, const void* gptr) {
    asm volatile("cp.async.cg.shared.global [%0], [%1], 16;"
                 :: "r"(smem_addr), "l"(gptr));
}

// ---------------------------------------------------------------------------
// Convert kernels: fp32 -> fp16
// ---------------------------------------------------------------------------
__global__ __launch_bounds__(256) void conv_h_kernel(const float* __restrict__ src)
{
    int i = blockIdx.x * 256 + threadIdx.x;
    float4 v = ((const float4*)src)[i];
    ((__half2*)g_h16)[2 * i] = __floats2half2_rn(v.x, v.y);
    ((__half2*)g_h16)[2 * i + 1] = __floats2half2_rn(v.z, v.w);
}
__global__ __launch_bounds__(256) void conv_w_kernel(const float* __restrict__ src)
{
    int i = blockIdx.x * 256 + threadIdx.x;
    float4 v = ((const float4*)src)[i];
    ((__half2*)g_w16)[2 * i] = __floats2half2_rn(v.x, v.y);
    ((__half2*)g_w16)[2 * i + 1] = __floats2half2_rn(v.z, v.w);
}

// ---------------------------------------------------------------------------
// Kernel 1: QKV projection on HMMA (unchanged from R8, verified 79us).
// ---------------------------------------------------------------------------
#define QKO_A 0
#define QKO_W 32768
#define QK_SMEM 65536

__global__ __launch_bounds__(256, 2) void qkv_mma_kernel(
    const float* __restrict__ bias)
{
    extern __shared__ char smem[];
    const uint32_t sb = smem_u32(smem);
    const int tid = threadIdx.x, wid = tid >> 5, lane = tid & 31;
    const int bx = blockIdx.x, by = blockIdx.y;
    const int m0 = (wid >> 1) * 32;
    const int wx = wid & 1;

    auto fill = [&](int s, int kt) {
        const uint32_t stgA = sb + QKO_A + s * 16384;
        const uint32_t stgW = sb + QKO_W + s * 16384;
#pragma unroll
        for (int j = 0; j < 4; j++) {
            int idx = tid + 256 * j;
            int row = idx >> 3, c = idx & 7;
            cp16(stgA + SW128((uint32_t)(row * 128 + c * 16)),
                 g_h16 + (size_t)(by * 128 + row) * HH + kt * 64 + c * 8);
        }
#pragma unroll
        for (int j = 0; j < 4; j++) {
            int idx = tid + 256 * j;
            int row = idx >> 4, c = idx & 15;
            cp16(stgW + (c >> 3) * 8192 + SW128((uint32_t)(row * 128 + (c & 7) * 16)),
                 g_w16 + (size_t)(kt * 64 + row) * 3072 + bx * 128 + c * 8);
        }
        asm volatile("cp.async.commit_group;" ::: "memory");
    };

    float acc[2][8][4];
#pragma unroll
    for (int i = 0; i < 2; i++)
#pragma unroll
        for (int j = 0; j < 8; j++)
#pragma unroll
            for (int c = 0; c < 4; c++) acc[i][j][c] = 0.f;

    const int aRow = lane & 15;
    const int aBx = (lane >> 4) * 16;

    fill(0, 0);
    fill(1, 1);

    for (int kt = 0; kt < 16; kt++) {
        if (kt < 15) asm volatile("cp.async.wait_group 1;" ::: "memory");
        else         asm volatile("cp.async.wait_group 0;" ::: "memory");
        __syncthreads();

        const uint32_t stgA = sb + QKO_A + (kt & 1) * 16384;
        const uint32_t wsub = sb + QKO_W + (kt & 1) * 16384 + wx * 8192;
#pragma unroll
        for (int ks = 0; ks < 4; ks++) {
            uint32_t Af[2][4], Bf[4][4];
#pragma unroll
            for (int mf = 0; mf < 2; mf++)
                ldsm4(Af[mf], stgA +
                      SW128((uint32_t)((m0 + mf * 16 + aRow) * 128 + ks * 32 + aBx)));
#pragma unroll
            for (int nt = 0; nt < 4; nt++)
                ldsm4t(Bf[nt], wsub +
                       SW128((uint32_t)((ks * 16 + aRow) * 128 + nt * 32 + aBx)));
#pragma unroll
            for (int mf = 0; mf < 2; mf++)
#pragma unroll
                for (int nf = 0; nf < 8; nf++)
                    mma_f16(acc[mf][nf], Af[mf], &Bf[nf >> 1][(nf & 1) * 2]);
        }
        __syncthreads();
        if (kt + 2 < 16) fill(kt & 1, kt + 2);
    }

    const int r = lane >> 2, c2 = 2 * (lane & 3);
#pragma unroll
    for (int nf = 0; nf < 8; nf++) {
        int n = bx * 128 + wx * 64 + nf * 8 + c2;
        float b0 = bias[n], b1 = bias[n + 1];
        int which = n >> 10;
        int h = (n & 1023) >> 6;
        int d = n & 63;
        __half* dst = (which == 0) ? g_qh : (which == 1) ? g_kh : g_vh;
#pragma unroll
        for (int mf = 0; mf < 2; mf++) {
            int m = by * 128 + m0 + mf * 16 + r;
            int b = m >> 11, s = m & 2047;
            size_t off = ((size_t)(b * NH + h) * SS + s) * HD + d;
            *(__half2*)(dst + off) =
                __floats2half2_rn(acc[mf][nf][0] + b0, acc[mf][nf][1] + b1);
            *(__half2*)(dst + off + (size_t)8 * HD) =
                __floats2half2_rn(acc[mf][nf][2] + b0, acc[mf][nf][3] + b1);
        }
    }
}

// ---------------------------------------------------------------------------
// Kernel 1b: dist_emb -> fp16 (row 4095 zero-padded)
// ---------------------------------------------------------------------------
__global__ __launch_bounds__(256) void split_e_kernel(const float* __restrict__ dist_emb)
{
    int i = blockIdx.x * 256 + threadIdx.x;
    if (i >= EROWS * HD) return;
    float e = (i < 4095 * HD) ? dist_emb[i] : 0.f;
    g_eh[i] = __float2half_rn(e);
}

// ---------------------------------------------------------------------------
// Kernel 2: persistent score kernel, 32-l-row tiles, 384 thr, 2 CTAs/SM.
// (verified R12/R13)  Writes RAW scores + g_rowstat.
// ---------------------------------------------------------------------------
#define SCQ 0
#define SCK 4096
#define SCE 20480
#define SCS 45056
#define SCQE 53760
#define SCKE 60416
#define SCMASK 73728
#define SC_SMEM 81920

__global__ __launch_bounds__(384, 2) void score_mma_kernel(
    const float* __restrict__ mask, float* __restrict__ probs)
{
    extern __shared__ char smem[];
    const uint32_t sb = smem_u32(smem);
    const int tid = threadIdx.x, wid = tid >> 5, lane = tid & 31;
    const int l0 = blockIdx.x * 32;
    const int z = blockIdx.y;

    for (int i = tid; i < 512; i += 384)
        ((float4*)(smem + SCMASK))[i] =
            ((const float4*)(mask + (size_t)(z / NH) * SS))[i];
    if (tid < 256) {
        int row = tid >> 3, c = tid & 7;
        uint32_t so = SW128((uint32_t)(row * 128 + c * 16));
        *(uint4*)(smem + SCQ + so) =
            *(const uint4*)(g_qh + ((size_t)z * SS + l0 + row) * HD + c * 8);
    }

    auto fill = [&](int s, int rt) {
        const uint32_t kbuf = sb + SCK + s * 8192;
        const uint32_t ebuf = sb + SCE + s * 12288;
        const int base2 = l0 - rt * 64 + 1984;
        for (int i = tid; i < 1280; i += 384) {
            if (i < 512) {
                int row = i >> 3, c = i & 7;
                cp16(kbuf + SW128((uint32_t)(row * 128 + c * 16)),
                     g_kh + ((size_t)z * SS + rt * 64 + row) * HD + c * 8);
            } else {
                int j = i - 512;
                int row = j >> 3, c = j & 7;
                cp16(ebuf + SW128((uint32_t)(row * 128 + c * 16)),
                     g_eh + (size_t)(base2 + row) * HD + c * 8);
            }
        }
        asm volatile("cp.async.commit_group;" ::: "memory");
    };

    fill(0, 0);
    fill(1, 1);

    const bool mma_act = (wid < 11);
    const bool aIsQ = (wid < 5);
    const int m0 = aIsQ ? 0 : ((wid - 5) & 1) * 32;
    const bool bIsK = (wid < 2);
    const int bn0 = (wid < 2) ? wid * 32
                  : (wid < 5) ? (wid - 2) * 32
                  : ((wid - 5) >> 1) * 32;

    const int aRow = lane & 15;
    const int aBx = (lane >> 4) * 16;
    const int bRow = (lane & 7) + (lane >> 4) * 8;
    const int bBx = ((lane >> 3) & 1) * 16;

    float om = -1e30f, os = 0.f;

    for (int r0 = 0; r0 < 32; r0++) {
        if (r0 < 31) asm volatile("cp.async.wait_group 1;" ::: "memory");
        else         asm volatile("cp.async.wait_group 0;" ::: "memory");
        __syncthreads();

        const int cur = r0 & 1;
        const uint32_t kbuf = sb + SCK + cur * 8192;
        const uint32_t ebuf = sb + SCE + cur * 12288;

        if (mma_act) {
            const uint32_t aBase = aIsQ ? (sb + SCQ) : kbuf;
            const uint32_t bBase = bIsK ? kbuf : ebuf;

            float acc[2][4][4];
#pragma unroll
            for (int i = 0; i < 2; i++)
#pragma unroll
                for (int j = 0; j < 4; j++)
#pragma unroll
                    for (int c = 0; c < 4; c++) acc[i][j][c] = 0.f;

#pragma unroll
            for (int ks = 0; ks < 4; ks++) {
                const int kb = ks * 32;
                uint32_t Af[2][4], Bf[2][4];
#pragma unroll
                for (int mf = 0; mf < 2; mf++)
                    ldsm4(Af[mf], aBase +
                          SW128((uint32_t)((m0 + mf * 16 + aRow) * 128 + kb + aBx)));
#pragma unroll
                for (int nt = 0; nt < 2; nt++)
                    ldsm4(Bf[nt], bBase +
                          SW128((uint32_t)((bn0 + nt * 16 + bRow) * 128 + kb + bBx)));
#pragma unroll
                for (int mf = 0; mf < 2; mf++)
#pragma unroll
                    for (int nf = 0; nf < 4; nf++)
                        mma_f16(acc[mf][nf], Af[mf], &Bf[nf >> 1][(nf & 1) * 2]);
            }

            const int r = lane >> 2, c2 = 2 * (lane & 3);
            if (bIsK) {
                float* sp = (float*)(smem + SCS);
#pragma unroll
                for (int mf = 0; mf < 2; mf++) {
                    int u = mf * 16 + r;
#pragma unroll
                    for (int nf = 0; nf < 4; nf++) {
                        int cc = bn0 + nf * 8 + c2;
                        *(float2*)&sp[u * 68 + cc] =
                            make_float2(acc[mf][nf][0], acc[mf][nf][1]);
                        *(float2*)&sp[(u + 8) * 68 + cc] =
                            make_float2(acc[mf][nf][2], acc[mf][nf][3]);
                    }
                }
            } else if (aIsQ) {
                __half* sp = (__half*)(smem + SCQE);
#pragma unroll
                for (int mf = 0; mf < 2; mf++) {
                    int u = mf * 16 + r;
#pragma unroll
                    for (int nf = 0; nf < 4; nf++) {
                        int cc = bn0 + nf * 8 + c2;
                        *(__half2*)&sp[u * 104 + cc] =
                            __floats2half2_rn(acc[mf][nf][0], acc[mf][nf][1]);
                        *(__half2*)&sp[(u + 8) * 104 + cc] =
                            __floats2half2_rn(acc[mf][nf][2], acc[mf][nf][3]);
                    }
                }
            } else {
                __half* sp = (__half*)(smem + SCKE);
#pragma unroll
                for (int mf = 0; mf < 2; mf++) {
                    int v = m0 + mf * 16 + r;
#pragma unroll
                    for (int nf = 0; nf < 4; nf++) {
                        int cc = bn0 + nf * 8 + c2;
                        *(__half2*)&sp[v * 104 + cc] =
                            __floats2half2_rn(acc[mf][nf][0], acc[mf][nf][1]);
                        *(__half2*)&sp[(v + 8) * 104 + cc] =
                            __floats2half2_rn(acc[mf][nf][2], acc[mf][nf][3]);
                    }
                }
            }
        }
        __syncthreads();

        if (r0 + 2 < 32) fill(cur, r0 + 2);

        if (tid < 256) {
            const float* Ss  = (const float*)(smem + SCS);
            const __half* QEs = (const __half*)(smem + SCQE);
            const __half* KEs = (const __half*)(smem + SCKE);
            const float* msk = (const float*)(smem + SCMASK);
            const int u = tid >> 3;
            const int v0 = (tid & 7) * 8;
            float* orow = probs + ((size_t)z * SS + l0 + u) * SS + r0 * 64;

            float4 o[2];
#pragma unroll
            for (int g = 0; g < 2; g++) {
                float* po = (float*)&o[g];
#pragma unroll
                for (int c = 0; c < 4; c++) {
                    int v = v0 + g * 4 + c;
                    int j = u - v + 63;
                    po[c] = 0.125f * Ss[u * 68 + v]
                          + __half2float(QEs[u * 104 + j])
                          + __half2float(KEs[v * 104 + j])
                          + msk[r0 * 64 + v];
                }
            }
            float tm = fmaxf(fmaxf(fmaxf(o[0].x, o[0].y), fmaxf(o[0].z, o[0].w)),
                             fmaxf(fmaxf(o[1].x, o[1].y), fmaxf(o[1].z, o[1].w)));
            float mn = fmaxf(om, tm);
            float add = __expf(o[0].x - mn) + __expf(o[0].y - mn)
                      + __expf(o[0].z - mn) + __expf(o[0].w - mn)
                      + __expf(o[1].x - mn) + __expf(o[1].y - mn)
                      + __expf(o[1].z - mn) + __expf(o[1].w - mn);
            os = os * __expf(om - mn) + add;
            om = mn;

            *(float4*)(orow + v0) = o[0];
            *(float4*)(orow + v0 + 4) = o[1];
        }
    }

    if (tid < 256) {
#pragma unroll
        for (int d = 4; d > 0; d >>= 1) {
            float m2 = __shfl_xor_sync(0xFFFFFFFF, om, d);
            float s2 = __shfl_xor_sync(0xFFFFFFFF, os, d);
            float mn = fmaxf(om, m2);
            os = os * __expf(om - mn) + s2 * __expf(m2 - mn);
            om = mn;
        }
        if ((tid & 7) == 0)
            g_rowstat[(size_t)z * SS + l0 + (tid >> 3)] = make_float2(om, 1.f / os);
    }
}

// ---------------------------------------------------------------------------
// Kernel 3: single-pass normalize (verified: DRAM-roofline).
// ---------------------------------------------------------------------------
__global__ __launch_bounds__(256) void normalize_kernel(float* __restrict__ probs)
{
    const int tid = threadIdx.x;
    const size_t row = blockIdx.x;
    const size_t rowb = row * SS;
    const float2 st = g_rowstat[row];
    const float m = st.x, inv = st.y;

    float4* p = (float4*)(probs + rowb);
    float4 x0 = p[tid];
    float4 x1 = p[tid + 256];

    x0.x = __expf(x0.x - m) * inv; x0.y = __expf(x0.y - m) * inv;
    x0.z = __expf(x0.z - m) * inv; x0.w = __expf(x0.w - m) * inv;
    x1.x = __expf(x1.x - m) * inv; x1.y = __expf(x1.y - m) * inv;
    x1.z = __expf(x1.z - m) * inv; x1.w = __expf(x1.w - m) * inv;

    p[tid] = x0;
    p[tid + 256] = x1;

    uint4 u;
    __half2* hp = (__half2*)&u;
    hp[0] = __floats2half2_rn(x0.x, x0.y);
    hp[1] = __floats2half2_rn(x0.z, x0.w);
    hp[2] = __floats2half2_rn(x1.x, x1.y);
    hp[3] = __floats2half2_rn(x1.z, x1.w);
    *(uint2*)(g_ph + rowb + tid * 4) = make_uint2(u.x, u.y);
    *(uint2*)(g_ph + rowb + 1024 + tid * 4) = make_uint2(u.z, u.w);
}

// ---------------------------------------------------------------------------
// Kernel 4: ctx = P @ V, k-chunk 128 (2 sub-tiles/stage), 2-stage cp.async.
// (verified R13)
// ---------------------------------------------------------------------------
#define PVS_P 0            // 2 x 16384 (sub-tiles: cols 0-63, 64-127 of chunk)
#define PVS_V 32768        // 2 x 8192  (sub-tiles: r 0-63, 64-127 of chunk)
#define PVS_STRIDE 49152
#define PV_SMEM (2 * PVS_STRIDE)

__global__ __launch_bounds__(256) void pv_mma_kernel(float* __restrict__ ctx)
{
    extern __shared__ char smem[];
    const uint32_t sb = smem_u32(smem);
    const int tid = threadIdx.x, wid = tid >> 5, lane = tid & 31;
    const int z = blockIdx.y;
    const int l0 = blockIdx.x * 128;
    const int m0 = (wid >> 1) * 32, d0 = (wid & 1) * 32;

    const size_t pbase = ((size_t)z * SS + l0) * SS;
    const size_t vbase = (size_t)z * SS * HD;

    auto fill = [&](int s, int kt) {
        const uint32_t stg = sb + s * PVS_STRIDE;
#pragma unroll
        for (int j = 0; j < 8; j++) {
            int idx = tid + 256 * j;
            int row = idx >> 4, c = idx & 15;
            cp16(stg + PVS_P + (c >> 3) * 16384 +
                     SW128((uint32_t)(row * 128 + (c & 7) * 16)),
                 g_ph + pbase + (size_t)row * SS + kt * 128 + c * 8);
        }
#pragma unroll
        for (int j = 0; j < 4; j++) {
            int idx = tid + 256 * j;
            int row = idx >> 3, c = idx & 7;
            cp16(stg + PVS_V + (row >> 6) * 8192 +
                     SW128((uint32_t)((row & 63) * 128 + c * 16)),
                 g_vh + vbase + (size_t)(kt * 128 + row) * HD + c * 8);
        }
        asm volatile("cp.async.commit_group;" ::: "memory");
    };

    float acc[2][4][4];
#pragma unroll
    for (int i = 0; i < 2; i++)
#pragma unroll
        for (int j = 0; j < 4; j++)
#pragma unroll
            for (int c = 0; c < 4; c++) acc[i][j][c] = 0.f;

    const int aRow = lane & 15;
    const int aBx = (lane >> 4) * 16;

    fill(0, 0);
    fill(1, 1);

    for (int rt = 0; rt < 16; rt++) {
        if (rt < 15) asm volatile("cp.async.wait_group 1;" ::: "memory");
        else         asm volatile("cp.async.wait_group 0;" ::: "memory");
        __syncthreads();

        const uint32_t stg = sb + (rt & 1) * PVS_STRIDE;
#pragma unroll
        for (int ksg = 0; ksg < 2; ksg++) {
            const uint32_t psub = stg + PVS_P + ksg * 16384;
            const uint32_t vsub = stg + PVS_V + ksg * 8192;
#pragma unroll
            for (int ks = 0; ks < 4; ks++) {
                const int kb = ks * 32;
                uint32_t Af[2][4], Bf[2][4];
#pragma unroll
                for (int mf = 0; mf < 2; mf++)
                    ldsm4(Af[mf], psub +
                          SW128((uint32_t)((m0 + mf * 16 + aRow) * 128 + kb + aBx)));
#pragma unroll
                for (int nt = 0; nt < 2; nt++)
                    ldsm4t(Bf[nt], vsub +
                           SW128((uint32_t)((ks * 16 + aRow) * 128 + (d0 + nt * 16) * 2 + aBx)));
#pragma unroll
                for (int mf = 0; mf < 2; mf++)
#pragma unroll
                    for (int nf = 0; nf < 4; nf++)
                        mma_f16(acc[mf][nf], Af[mf], &Bf[nf >> 1][(nf & 1) * 2]);
            }
        }
        __syncthreads();
        if (rt + 2 < 16) fill(rt & 1, rt + 2);
    }

    const int b = z / NH, h = z % NH;
    const int r = lane >> 2, c2 = 2 * (lane & 3);
#pragma unroll
    for (int mf = 0; mf < 2; mf++) {
        int l = l0 + m0 + mf * 16 + r;
#pragma unroll
        for (int nf = 0; nf < 4; nf++) {
            int d = d0 + nf * 8 + c2;
            float* o = ctx + ((size_t)b * SS + l) * HH + h * HD + d;
            *(float2*)o = make_float2(acc[mf][nf][0], acc[mf][nf][1]);
            *(float2*)(o + (size_t)8 * HH) = make_float2(acc[mf][nf][2], acc[mf][nf][3]);
        }
    }
}

// ---------------------------------------------------------------------------
extern "C" void kernel_launch(void* const* d_in, const int* in_sizes, int n_in,
                              void* d_out, int out_size)
{
    const float* hidden   = (const float*)d_in[0];
    const float* mask     = (const float*)d_in[1];
    const float* qkv_w    = (const float*)d_in[2];
    const float* qkv_b    = (const float*)d_in[3];
    const float* dist_emb = (const float*)d_in[4];

    float* out = (float*)d_out;
    float* ctx = out;
    float* probs = out + (size_t)BB * SS * HH;

    // 1) fp16 conversions of GEMM inputs + E table
    conv_h_kernel<<<BB * SS * HH / 1024, 256>>>(hidden);
    conv_w_kernel<<<HH * 3 * HH / 1024, 256>>>(qkv_w);
    split_e_kernel<<<(EROWS * HD + 255) / 256, 256>>>(dist_emb);

    // 2) QKV projection on HMMA -> g_qh/g_kh/g_vh
    cudaFuncSetAttribute(qkv_mma_kernel,
                         cudaFuncAttributeMaxDynamicSharedMemorySize, QK_SMEM);
    qkv_mma_kernel<<<dim3(3072 / 128, 4096 / 128), 256, QK_SMEM>>>(qkv_b);

    // 3) persistent warp-MMA scores (32-l tiles, 2 CTAs/SM) -> raw probs + stats
    cudaFuncSetAttribute(score_mma_kernel,
                         cudaFuncAttributeMaxDynamicSharedMemorySize, SC_SMEM);
    score_mma_kernel<<<dim3(SS / 32, ZT), 384, SC_SMEM>>>(mask, probs);

    // 4) single-pass normalize -> fp32 probs + fp16 g_ph
    normalize_kernel<<<ZT * SS, 256>>>(probs);

    // 5) ctx = probs @ v (k-chunk 128, 2-stage)
    cudaFuncSetAttribute(pv_mma_kernel,
                         cudaFuncAttributeMaxDynamicSharedMemorySize, PV_SMEM);
    pv_mma_kernel<<<dim3(SS / 128, ZT), 256, PV_SMEM>>>(ctx);
}